// round 17
// baseline (speedup 1.0000x reference)
#include <cuda_runtime.h>
#include <cuda_fp16.h>
#include <cstdint>

#define E_TOTAL 160000
#define NNODES  10000
#define NBLK    2500
#define TEDGE   64

#define SP   136
#define SPB  272
#define ABUF (64 * SPB)          // 17408: EA tile (later merge buffer)
#define WBUF (64 * SPB)          // 17408: one n64 x k128 weight chunk

#define EA_OFF  0
#define WB_OFF  ABUF             // 3 contiguous ring buffers (W1 uses buf0+buf1)
#define FL_OFF  (ABUF + 3*WBUF)  // 69632
// float-indexed offsets in FL region
#define SA0  0                   // x0*sh0    [64][16] f32
#define SA1  1024                // x0        [64][16] f32
#define SA3  2048                // dot/sqrt3 [64][16] f32
#define SX1  3072                // x1        [64][48] f32
#define SSH  6144                // sh        [64][4]  f32
#define SDST 6400                // int [64]
#define SSRC 6464                // int [64]
#define SB1  6528                // b1 [128]
#define SB2  6656                // b2 [1024]
#define NFL  7680
#define SMEM_BYTES (FL_OFF + NFL * 4)   // 100352 -> 2 CTAs/SM

__device__ float g_acc[NNODES * 64];
__device__ float g_cnt[NNODES];
__device__ __align__(16) unsigned char g_w1s[128 * SPB];     // W1T fp16
__device__ __align__(16) unsigned char g_w2s[16][64 * SPB];  // 16 n64-chunks of W2T

__device__ __forceinline__ uint32_t smem_u32(const void* p) {
    uint32_t a;
    asm("{ .reg .u64 t; cvta.to.shared.u64 t, %1; cvt.u32.u64 %0, t; }" : "=r"(a) : "l"(p));
    return a;
}
__device__ __forceinline__ void ldsm_x4(uint32_t* r, uint32_t addr) {
    asm volatile("ldmatrix.sync.aligned.m8n8.x4.shared.b16 {%0,%1,%2,%3}, [%4];"
        : "=r"(r[0]), "=r"(r[1]), "=r"(r[2]), "=r"(r[3]) : "r"(addr));
}
__device__ __forceinline__ void mma16816(float* c, const uint32_t* a, const uint32_t* b) {
    asm volatile("mma.sync.aligned.m16n8k16.row.col.f32.f16.f16.f32 "
        "{%0,%1,%2,%3}, {%4,%5,%6,%7}, {%8,%9}, {%0,%1,%2,%3};"
        : "+f"(c[0]), "+f"(c[1]), "+f"(c[2]), "+f"(c[3])
        : "r"(a[0]), "r"(a[1]), "r"(a[2]), "r"(a[3]), "r"(b[0]), "r"(b[1]));
}
__device__ __forceinline__ uint32_t pkh(float a, float b) {
    __half2 h = __floats2half2_rn(a, b);
    return *(uint32_t*)&h;
}
__device__ __forceinline__ void cp16(uint32_t dst, const void* src) {
    asm volatile("cp.async.cg.shared.global [%0], [%1], 16;" :: "r"(dst), "l"(src));
}
#define CP_COMMIT() asm volatile("cp.async.commit_group;" ::: "memory")
#define CP_WAIT(n)  asm volatile("cp.async.wait_group %0;" :: "n"(n) : "memory")

__global__ void zero_kernel() {
    int i = blockIdx.x * blockDim.x + threadIdx.x;
    if (i < NNODES * 64) g_acc[i] = 0.0f;
    else if (i < NNODES * 64 + NNODES) g_cnt[i - NNODES * 64] = 0.0f;
}

__global__ void prep_w1(const float* __restrict__ w1) {
    int t = blockIdx.x * 256 + threadIdx.x;
    if (t >= 128 * 64) return;
    int h = t >> 6, f = (t & 63) * 2;
    *(uint32_t*)(g_w1s + (uint32_t)h * SPB + (uint32_t)f * 2) =
        pkh(w1[f * 128 + h], w1[(f + 1) * 128 + h]);
}

__global__ void prep_w2(const float* __restrict__ w2) {
    int t = blockIdx.x * 256 + threadIdx.x;
    if (t >= 16 * 64 * 64) return;
    int c = t >> 12, n = (t >> 6) & 63, f = (t & 63) * 2;
    int kg = c * 64 + n;
    *(uint32_t*)(g_w2s[c] + (uint32_t)n * SPB + (uint32_t)f * 2) =
        pkh(w2[f * 1024 + kg], w2[(f + 1) * 1024 + kg]);
}

// ---------------- main fused kernel: 256 threads, 4m x 2kq warp grid ----------------
__global__ void __launch_bounds__(256, 2) fused_kernel(
    const float* __restrict__ x,  const int* __restrict__ ei,
    const float* __restrict__ ea, const float* __restrict__ esh,
    const float* __restrict__ b1, const float* __restrict__ b2)
{
    extern __shared__ unsigned char sm[];
    unsigned char* EAc = sm + EA_OFF;
    float* F   = (float*)(sm + FL_OFF);
    float* Sa0 = F + SA0;
    float* Sa1 = F + SA1;
    float* Sa3 = F + SA3;
    float* Sx1 = F + SX1;
    float* Ssh = F + SSH;
    int* Sdst  = (int*)(F + SDST);
    int* Ssrc  = (int*)(F + SSRC);
    float* b1s = F + SB1;
    float* b2s = F + SB2;
    float* Mg  = (float*)(sm + EA_OFF);     // merge buffer aliases EA (dead after GEMM1)

    const int tid = threadIdx.x;
    const int wid = tid >> 5, lid = tid & 31;
    const int e0  = blockIdx.x * TEDGE;
    const uint32_t sb = smem_u32(sm);

    const int mg = wid & 3;                 // m-group (16 edges)
    const int kq = wid >> 2;                // c-half / k-split of GEMM2
    const int r0 = mg * 16 + (lid >> 2), r1 = r0 + 8;
    const int cb = (lid & 3) * 2;
    const uint32_t aoff = (uint32_t)(mg * 16 + (lid & 15)) * SPB + (uint32_t)(lid >> 4) * 16;

    // prefetch: G0 = W1 -> buf0+buf1, G1 = W2[0] -> buf2
    #pragma unroll
    for (int i = 0; i < 9; i++) {
        uint32_t o = (uint32_t)(tid + i * 256) * 16;
        if (o < 2 * WBUF) cp16(sb + WB_OFF + o, g_w1s + o);
    }
    CP_COMMIT();
    #pragma unroll
    for (int i = 0; i < 5; i++) {
        uint32_t o = (uint32_t)(tid + i * 256) * 16;
        if (o < WBUF) cp16(sb + WB_OFF + 2 * WBUF + o, g_w2s[0] + o);
    }
    CP_COMMIT();

    // biases + indices + sh
    if (tid < 128) b1s[tid] = b1[tid];
    #pragma unroll
    for (int i = 0; i < 4; i++) b2s[tid + i * 256] = b2[tid + i * 256];
    if (tid < TEDGE) {
        int eg = e0 + tid;
        Ssrc[tid] = ei[eg];
        Sdst[tid] = ei[E_TOTAL + eg];
        float4 s = *(const float4*)(esh + (size_t)eg * 4);
        Ssh[tid*4+0] = s.x; Ssh[tid*4+1] = s.y; Ssh[tid*4+2] = s.z; Ssh[tid*4+3] = s.w;
    }
    __syncthreads();

    // gather x[src] + TP precompute (f32 tables)
    {
        int e = tid & 63, part = tid >> 6;
        if (part < 2) {
            int src = Ssrc[e];
            const float4* xr = (const float4*)(x + (size_t)src * 64);
            if (part == 0) {
                float sh0 = Ssh[e*4];
                #pragma unroll
                for (int q = 0; q < 4; q++) {
                    float4 xv = xr[q];
                    int u = q * 4;
                    Sa1[e*16+u+0] = xv.x;  Sa0[e*16+u+0] = xv.x * sh0;
                    Sa1[e*16+u+1] = xv.y;  Sa0[e*16+u+1] = xv.y * sh0;
                    Sa1[e*16+u+2] = xv.z;  Sa0[e*16+u+2] = xv.z * sh0;
                    Sa1[e*16+u+3] = xv.w;  Sa0[e*16+u+3] = xv.w * sh0;
                }
            } else {
                float s1x = Ssh[e*4+1], s1y = Ssh[e*4+2], s1z = Ssh[e*4+3];
                float x1l[48];
                #pragma unroll
                for (int q = 0; q < 12; q++) {
                    float4 xv = xr[4 + q];
                    x1l[q*4+0]=xv.x; x1l[q*4+1]=xv.y; x1l[q*4+2]=xv.z; x1l[q*4+3]=xv.w;
                    *(float4*)(Sx1 + e*48 + q*4) = xv;
                }
                #pragma unroll
                for (int u = 0; u < 16; u++) {
                    float d = x1l[u*3]*s1x + x1l[u*3+1]*s1y + x1l[u*3+2]*s1z;
                    Sa3[e*16+u] = d * 0.57735026918962576f;
                }
            }
        }
    }

    // EA tile -> fp16 (quarter row per thread)
    {
        int r = tid >> 2, q = tid & 3;
        const float4* rowp = (const float4*)(ea + (size_t)(e0 + r) * 128 + q * 32);
        uint32_t* dst = (uint32_t*)(EAc + (uint32_t)r * SPB + (uint32_t)(q * 32) * 2);
        #pragma unroll
        for (int j = 0; j < 8; j++) {
            float4 v = rowp[j];
            dst[j*2]     = pkh(v.x, v.y);
            dst[j*2 + 1] = pkh(v.z, v.w);
        }
    }

    // GEMM1: H-half (c in [kq*64, kq*64+64)) = EA @ W1-half ; result stays in registers
    CP_WAIT(1);     // W1 resident (W2[0] may still be in flight)
    __syncthreads();

    float acc1[8][4];
    #pragma unroll
    for (int nt = 0; nt < 8; nt++)
        #pragma unroll
        for (int q = 0; q < 4; q++) acc1[nt][q] = 0.0f;

    {
        uint32_t w1b = sb + WB_OFF + (uint32_t)(kq * 64 + (lid & 7)) * SPB
                     + (uint32_t)(lid >> 3) * 16;
        #pragma unroll
        for (int kp = 0; kp < 4; kp++) {
            uint32_t Am[8];
            ldsm_x4(Am,     sb + EA_OFF + aoff + kp * 64);
            ldsm_x4(Am + 4, sb + EA_OFF + aoff + kp * 64 + 32);
            #pragma unroll
            for (int nt = 0; nt < 8; nt++) {
                uint32_t Bf[4];
                ldsm_x4(Bf, w1b + (uint32_t)nt * (8 * SPB) + kp * 64);
                mma16816(acc1[nt], Am,     Bf);
                mma16816(acc1[nt], Am + 4, Bf + 2);
            }
        }
    }
    __syncthreads();   // EA + W1 buffers free

    // prefetch W2[1]->buf0 (G2), W2[2]->buf1 (G3)
    #pragma unroll
    for (int i = 0; i < 5; i++) {
        uint32_t o = (uint32_t)(tid + i * 256) * 16;
        if (o < WBUF) cp16(sb + WB_OFF + o, g_w2s[1] + o);
    }
    CP_COMMIT();
    #pragma unroll
    for (int i = 0; i < 5; i++) {
        uint32_t o = (uint32_t)(tid + i * 256) * 16;
        if (o < WBUF) cp16(sb + WB_OFF + WBUF + o, g_w2s[2] + o);
    }
    CP_COMMIT();

    // pack H (bias+relu) into A-fragment registers: D-frag == A-frag layout
    uint32_t Hreg[16];
    #pragma unroll
    for (int j = 0; j < 4; j++) {
        int ntA = 2*j, ntB = 2*j + 1;
        float bA0 = b1s[kq*64 + ntA*8 + cb], bA1 = b1s[kq*64 + ntA*8 + cb + 1];
        float bB0 = b1s[kq*64 + ntB*8 + cb], bB1 = b1s[kq*64 + ntB*8 + cb + 1];
        Hreg[4*j+0] = pkh(fmaxf(acc1[ntA][0]+bA0, 0.f), fmaxf(acc1[ntA][1]+bA1, 0.f));
        Hreg[4*j+1] = pkh(fmaxf(acc1[ntA][2]+bA0, 0.f), fmaxf(acc1[ntA][3]+bA1, 0.f));
        Hreg[4*j+2] = pkh(fmaxf(acc1[ntB][0]+bB0, 0.f), fmaxf(acc1[ntB][1]+bB1, 0.f));
        Hreg[4*j+3] = pkh(fmaxf(acc1[ntB][2]+bB0, 0.f), fmaxf(acc1[ntB][3]+bB1, 0.f));
    }

    // GEMM2: 16 n64-chunks, A = Hreg (k-split by kq), B from 3-deep ring
    float s0[2][4], t1[2][4], o1[2][4][3];
    #pragma unroll
    for (int er = 0; er < 2; er++)
        #pragma unroll
        for (int vi = 0; vi < 4; vi++) {
            s0[er][vi] = 0.0f; t1[er][vi] = 0.0f;
            o1[er][vi][0] = 0.0f; o1[er][vi][1] = 0.0f; o1[er][vi][2] = 0.0f;
        }

    const uint32_t bq = (uint32_t)(lid & 7) * SPB + (uint32_t)kq * 128
                      + (uint32_t)(lid >> 3) * 16;

    #pragma unroll 1
    for (int ch = 0; ch < 16; ch++) {
        CP_WAIT(3);         // retires exactly through group ch+1 (= W2[ch])
        __syncthreads();

        float acc[8][4];
        #pragma unroll
        for (int nt = 0; nt < 8; nt++)
            #pragma unroll
            for (int q = 0; q < 4; q++) acc[nt][q] = 0.0f;

        uint32_t wb = sb + WB_OFF + (uint32_t)((ch + 2) % 3) * WBUF + bq;
        #pragma unroll
        for (int kp2 = 0; kp2 < 2; kp2++) {
            #pragma unroll
            for (int nt = 0; nt < 8; nt++) {
                uint32_t Bf[4];
                ldsm_x4(Bf, wb + (uint32_t)nt * (8 * SPB) + kp2 * 64);
                mma16816(acc[nt], Hreg + kp2*8,     Bf);
                mma16816(acc[nt], Hreg + kp2*8 + 4, Bf + 2);
            }
        }

        // bias pre-add (kq==0 only) — TP loops consume acc directly
        if (kq == 0) {
            const float* b2c = b2s + ch * 64;
            #pragma unroll
            for (int nt = 0; nt < 8; nt++) {
                float bb0 = b2c[nt*8 + cb], bb1 = b2c[nt*8 + cb + 1];
                acc[nt][0] += bb0; acc[nt][1] += bb1;
                acc[nt][2] += bb0; acc[nt][3] += bb1;
            }
        }

        // TP: k = ch*64 + nt*8 + cb + d ; p = ch>>2 ; u = (ch&3)*4 + (nt>>1) ; v = (nt&1)*8+cb+d
        const int p  = ch >> 2;
        const int ub = (ch & 3) * 4;

        if (p == 2) {
            #pragma unroll
            for (int nt = 0; nt < 8; nt++) {
                int u = ub + (nt >> 1);
                float xa0 = Sx1[r0*48 + u*3 + 0], xb0 = Sx1[r0*48 + u*3 + 1], xc0 = Sx1[r0*48 + u*3 + 2];
                float xa1 = Sx1[r1*48 + u*3 + 0], xb1 = Sx1[r1*48 + u*3 + 1], xc1 = Sx1[r1*48 + u*3 + 2];
                #pragma unroll
                for (int d = 0; d < 2; d++) {
                    int vi = (nt & 1) * 2 + d;
                    float w0 = acc[nt][d];
                    float w1 = acc[nt][2 + d];
                    o1[0][vi][0] = fmaf(xa0, w0, o1[0][vi][0]);
                    o1[0][vi][1] = fmaf(xb0, w0, o1[0][vi][1]);
                    o1[0][vi][2] = fmaf(xc0, w0, o1[0][vi][2]);
                    o1[1][vi][0] = fmaf(xa1, w1, o1[1][vi][0]);
                    o1[1][vi][1] = fmaf(xb1, w1, o1[1][vi][1]);
                    o1[1][vi][2] = fmaf(xc1, w1, o1[1][vi][2]);
                }
            }
        } else {
            const float* A = (p == 0) ? Sa0 : (p == 1) ? Sa1 : Sa3;
            float a0[4], a1[4];
            #pragma unroll
            for (int u = 0; u < 4; u++) {
                a0[u] = A[r0*16 + ub + u];
                a1[u] = A[r1*16 + ub + u];
            }
            if (p == 1) {
                #pragma unroll
                for (int nt = 0; nt < 8; nt++) {
                    int u = nt >> 1;
                    #pragma unroll
                    for (int d = 0; d < 2; d++) {
                        int vi = (nt & 1) * 2 + d;
                        t1[0][vi] = fmaf(a0[u], acc[nt][d],     t1[0][vi]);
                        t1[1][vi] = fmaf(a1[u], acc[nt][2 + d], t1[1][vi]);
                    }
                }
            } else {
                #pragma unroll
                for (int nt = 0; nt < 8; nt++) {
                    int u = nt >> 1;
                    #pragma unroll
                    for (int d = 0; d < 2; d++) {
                        int vi = (nt & 1) * 2 + d;
                        s0[0][vi] = fmaf(a0[u], acc[nt][d],     s0[0][vi]);
                        s0[1][vi] = fmaf(a1[u], acc[nt][2 + d], s0[1][vi]);
                    }
                }
            }
        }
        __syncthreads();   // buffer reads done before refill

        // refill buffer just read with W2[ch+3]; ALWAYS commit (empty groups keep ring math)
        if (ch + 3 <= 15) {
            const unsigned char* s2 = g_w2s[ch + 3];
            uint32_t dsto = WB_OFF + (uint32_t)((ch + 2) % 3) * WBUF;
            #pragma unroll
            for (int i = 0; i < 5; i++) {
                uint32_t o = (uint32_t)(tid + i * 256) * 16;
                if (o < WBUF) cp16(sb + dsto + o, s2 + o);
            }
        }
        CP_COMMIT();
    }

    // 2-way kq merge in SMEM (Mg aliases EA buffer), then scatter-add
    {
        if (kq == 0) {
            #pragma unroll
            for (int er = 0; er < 2; er++) {
                int e = er ? r1 : r0;
                float sh0 = Ssh[e*4+0];
                float s1x = Ssh[e*4+1], s1y = Ssh[e*4+2], s1z = Ssh[e*4+3];
                float* mrow = Mg + e * 64;
                #pragma unroll
                for (int vi = 0; vi < 4; vi++) {
                    int v = cb + (vi >> 1) * 8 + (vi & 1);
                    mrow[v]            = s0[er][vi];
                    mrow[16 + v*3 + 0] = t1[er][vi]*s1x + sh0*o1[er][vi][0];
                    mrow[16 + v*3 + 1] = t1[er][vi]*s1y + sh0*o1[er][vi][1];
                    mrow[16 + v*3 + 2] = t1[er][vi]*s1z + sh0*o1[er][vi][2];
                }
            }
        }
        __syncthreads();
        if (kq == 1) {
            const float alpha = 0.17677669529663689f;  // 1/sqrt(2*16)
            #pragma unroll
            for (int er = 0; er < 2; er++) {
                int e = er ? r1 : r0;
                int dst = Sdst[e];
                float sh0 = Ssh[e*4+0];
                float s1x = Ssh[e*4+1], s1y = Ssh[e*4+2], s1z = Ssh[e*4+3];
                float* mrow = Mg + e * 64;
                float* base = g_acc + (size_t)dst * 64;
                #pragma unroll
                for (int vi = 0; vi < 4; vi++) {
                    int v = cb + (vi >> 1) * 8 + (vi & 1);
                    atomicAdd(base + v, alpha * (s0[er][vi] + mrow[v]));
                    atomicAdd(base + 16 + v*3 + 0,
                        alpha * (t1[er][vi]*s1x + sh0*o1[er][vi][0] + mrow[16 + v*3 + 0]));
                    atomicAdd(base + 16 + v*3 + 1,
                        alpha * (t1[er][vi]*s1y + sh0*o1[er][vi][1] + mrow[16 + v*3 + 1]));
                    atomicAdd(base + 16 + v*3 + 2,
                        alpha * (t1[er][vi]*s1z + sh0*o1[er][vi][2] + mrow[16 + v*3 + 2]));
                }
                if ((lid & 3) == 0) atomicAdd(&g_cnt[dst], 1.0f);
            }
        }
    }
}

__global__ void finalize_kernel(const float* __restrict__ x, float* __restrict__ out) {
    int i = blockIdx.x * blockDim.x + threadIdx.x;
    if (i < NNODES * 64) {
        int node = i >> 6;
        out[i] = g_acc[i] / fmaxf(g_cnt[node], 1.0f) + x[i];
    }
}

extern "C" void kernel_launch(void* const* d_in, const int* in_sizes, int n_in,
                              void* d_out, int out_size)
{
    const float* x   = (const float*)d_in[0];
    const int*   ei  = (const int*)  d_in[1];
    const float* ea  = (const float*)d_in[2];
    const float* esh = (const float*)d_in[3];
    const float* w1  = (const float*)d_in[4];
    const float* b1  = (const float*)d_in[5];
    const float* w2  = (const float*)d_in[6];
    const float* b2  = (const float*)d_in[7];
    float* out = (float*)d_out;

    cudaFuncSetAttribute(fused_kernel,
                         cudaFuncAttributeMaxDynamicSharedMemorySize, SMEM_BYTES);

    int ztot = NNODES * 64 + NNODES;
    zero_kernel<<<(ztot + 255) / 256, 256>>>();
    prep_w1<<<(128 * 64 + 255) / 256, 256>>>(w1);
    prep_w2<<<(16 * 64 * 64 + 255) / 256, 256>>>(w2);
    fused_kernel<<<NBLK, 256, SMEM_BYTES>>>(x, ei, ea, esh, b1, b2);
    finalize_kernel<<<(NNODES * 64 + 255) / 256, 256>>>(x, out);
}